// round 7
// baseline (speedup 1.0000x reference)
#include <cuda_runtime.h>
#include <cuda_fp16.h>
#include <cstdint>

#define N_TOK 8192
#define CDIM  1024
#define HDIM  4096
#define NEXP  8
#define BM    128
#define BK    32
#define MAXTILES 80
#define ASTRIDE 40    // halves per A smem row (80 B): conflict-free ldsm
#define BSTRIDE 136   // halves per B smem row (272 B): conflict-free ldsm

#define ROUTER_BLKS 1024          // 8 warps/CTA, 1 token/warp
#define W1CVT_BLKS  288
#define XCVT_BLKS   128
#define W2CVT_BLKS  288           // extra CTAs inside gemm0
#define W_N4 (NEXP * CDIM * HDIM / 4)   // float4 count per weight tensor
#define X_N4 (N_TOK * CDIM / 4)

// ---- scratch (static __device__ — allocation-free per harness rules) ----
__device__ __half g_hh [(size_t)N_TOK * HDIM];           // fc1 act (fp16), sorted order
__device__ __half g_xh [(size_t)N_TOK * CDIM];           // x in fp16
__device__ __half g_w1h[(size_t)NEXP * CDIM * HDIM];     // W1 fp16
__device__ __half g_w2h[(size_t)NEXP * HDIM * CDIM];     // W2 fp16
__device__ int    g_idx[N_TOK];
__device__ float  g_prob[N_TOK];
__device__ int    g_perm[N_TOK];
__device__ int    g_counts[NEXP];
__device__ int    g_cursor[NEXP];
__device__ int    g_offset[NEXP + 1];
__device__ int    g_tileExpert[MAXTILES];
__device__ int    g_tileStart[MAXTILES];
__device__ int    g_tileCount[MAXTILES];
__device__ int    g_numTiles;

// ---------------------------------------------------------------- helpers
__device__ __forceinline__ float gelu_f(float v) {
    return 0.5f * v * (1.0f + erff(v * 0.70710678118654752f));
}
__device__ __forceinline__ void cp16(uint32_t dst, const void* src, bool pred) {
    int sz = pred ? 16 : 0;  // src-size 0 => zero-fill 16B
    asm volatile("cp.async.ca.shared.global [%0], [%1], 16, %2;\n"
                 :: "r"(dst), "l"(src), "r"(sz));
}
__device__ __forceinline__ void ldsm4(uint32_t& r0, uint32_t& r1, uint32_t& r2,
                                      uint32_t& r3, uint32_t addr) {
    asm volatile("ldmatrix.sync.aligned.m8n8.x4.shared.b16 {%0,%1,%2,%3}, [%4];"
                 : "=r"(r0), "=r"(r1), "=r"(r2), "=r"(r3) : "r"(addr));
}
__device__ __forceinline__ void ldsm4t(uint32_t& r0, uint32_t& r1, uint32_t& r2,
                                       uint32_t& r3, uint32_t addr) {
    asm volatile("ldmatrix.sync.aligned.m8n8.x4.trans.shared.b16 {%0,%1,%2,%3}, [%4];"
                 : "=r"(r0), "=r"(r1), "=r"(r2), "=r"(r3) : "r"(addr));
}
// grid-stride fp32 -> fp16 convert over a block-partitioned range
__device__ __forceinline__ void conv_range(const float* __restrict__ src,
                                           __half* __restrict__ dst, int n4,
                                           int blk, int nblk) {
    const float4* s = (const float4*)src;
    __half2* d = (__half2*)dst;
    int stride = nblk * blockDim.x;
    for (int i = blk * blockDim.x + threadIdx.x; i < n4; i += stride) {
        float4 v = s[i];
        d[2 * i]     = __floats2half2_rn(v.x, v.y);
        d[2 * i + 1] = __floats2half2_rn(v.z, v.w);
    }
}

// ---------------------------------------------------------------- small kernels
__global__ void init_k() {
    int t = threadIdx.x;
    if (t < NEXP) { g_counts[t] = 0; g_cursor[t] = 0; }
}

// fused: router (blocks [0,1024)) + W1 convert + x convert
__global__ void prep_k(const float* __restrict__ x, const float* __restrict__ Wr,
                       const float* __restrict__ br, const float* __restrict__ W1,
                       __half* __restrict__ w1h, __half* __restrict__ xh) {
    int b = blockIdx.x;
    if (b >= ROUTER_BLKS) {
        int cb = b - ROUTER_BLKS;
        if (cb < W1CVT_BLKS) conv_range(W1, w1h, W_N4, cb, W1CVT_BLKS);
        else conv_range(x, xh, X_N4, cb - W1CVT_BLKS, XCVT_BLKS);
        return;
    }
    int gt = b * blockDim.x + threadIdx.x;
    int tok = gt >> 5, lane = gt & 31;
    const float* xr = x + (size_t)tok * CDIM;
    float s[NEXP];
#pragma unroll
    for (int e = 0; e < NEXP; e++) s[e] = 0.f;
    for (int k = lane; k < CDIM; k += 32) {
        float xv = xr[k];
        const float4* w = (const float4*)(Wr + (size_t)k * NEXP);
        float4 w0 = w[0], w1 = w[1];
        s[0] += xv * w0.x; s[1] += xv * w0.y; s[2] += xv * w0.z; s[3] += xv * w0.w;
        s[4] += xv * w1.x; s[5] += xv * w1.y; s[6] += xv * w1.z; s[7] += xv * w1.w;
    }
#pragma unroll
    for (int e = 0; e < NEXP; e++)
#pragma unroll
        for (int o = 16; o > 0; o >>= 1) s[e] += __shfl_xor_sync(0xffffffffu, s[e], o);
    if (lane == 0) {
        float l[NEXP];
        l[0] = s[0] + br[0];
        float m = l[0]; int mi = 0;
#pragma unroll
        for (int e = 1; e < NEXP; e++) {
            l[e] = s[e] + br[e];
            if (l[e] > m) { m = l[e]; mi = e; }
        }
        float sum = 0.f;
#pragma unroll
        for (int e = 0; e < NEXP; e++) sum += expf(l[e] - m);
        g_prob[tok] = 1.0f / sum;
        g_idx[tok] = mi;
        atomicAdd(&g_counts[mi], 1);
    }
}

__global__ void setup_k(float* out, int out_size) {
    if (threadIdx.x != 0 || blockIdx.x != 0) return;
    int off = 0, nt = 0;
    for (int e = 0; e < NEXP; e++) {
        g_offset[e] = off;
        int c = g_counts[e];
        int t = (c + BM - 1) / BM;
        for (int i = 0; i < t; i++) {
            g_tileExpert[nt] = e;
            g_tileStart[nt] = off + i * BM;
            int rem = c - i * BM;
            g_tileCount[nt] = rem < BM ? rem : BM;
            nt++;
        }
        off += c;
    }
    g_offset[NEXP] = off;
    g_numTiles = nt;
    float aux = 0.f, tot = (float)off;
    if (tot < 1.f) tot = 1.f;
    for (int e = 0; e < NEXP; e++) {
        float d = (float)g_counts[e] / tot - 1.0f / NEXP;
        aux += d * d;
    }
    aux *= 1.0f / NEXP;
    if (out_size > N_TOK * CDIM) out[(size_t)N_TOK * CDIM] = aux;
}

__global__ void scatter_k() {
    int t = blockIdx.x * blockDim.x + threadIdx.x;
    if (t >= N_TOK) return;
    int e = g_idx[t];
    int p = atomicAdd(&g_cursor[e], 1);
    g_perm[g_offset[e] + p] = t;
}

// ---------------------------------------------------------------- fp16 grouped GEMM
// 8 warps = 4(M) x 2(N); warp tile 32 x 64; CTA tile 128 x 128, BK=32 halves.
// MODE 0: g_hh = fp16(gelu(g_xh[perm] @ W1[e] + b1[e]))  K=1024, NDIM=4096
//         + 288 trailing CTAs (mt >= 72) convert W2 fp32->fp16 concurrently.
// MODE 1: out[token] = prob * (g_hh @ W2[e] + b2[e])     K=4096, NDIM=1024
template <int MODE>
__global__ void __launch_bounds__(256)
moe_gemm_k(const __half* __restrict__ Ain, const __half* __restrict__ W,
           const float* __restrict__ bias, float* __restrict__ OutG,
           const float* __restrict__ CvtSrc, __half* __restrict__ CvtDst,
           int K, int NDIM) {
    __shared__ __half As[2][BM * ASTRIDE];
    __shared__ __half Bs[2][BK * BSTRIDE];

    int mt = blockIdx.x;
    if (MODE == 0 && mt >= 72) {
        int cb = (mt - 72) * gridDim.y + blockIdx.y;   // 9 x 32 = 288 blocks
        conv_range(CvtSrc, CvtDst, W_N4, cb, W2CVT_BLKS);
        return;
    }
    if (mt >= g_numTiles) return;
    int e      = g_tileExpert[mt];
    int gstart = g_tileStart[mt];
    int mcount = g_tileCount[mt];
    int n0     = blockIdx.y * 128;

    const __half* We = W + (size_t)e * K * NDIM;

    int tid = threadIdx.x, lane = tid & 31, warp = tid >> 5;
    int wm = warp & 3;        // 4 warps along M (32 rows)
    int wn = warp >> 2;       // 2 warps along N (64 cols)
    int gid = lane >> 2, tig = lane & 3;

    // ---- A loads: row = tid>>1, 32B of the 64B row per thread (2 x cp16)
    int arow = tid >> 1;
    int ach  = (tid & 1) * 16;
    bool va  = arow < mcount;
    const __half* pA;
    if (MODE == 0) {
        int t0 = va ? g_perm[gstart + arow] : g_perm[gstart];
        pA = Ain + (size_t)t0 * K + ach;
    } else {
        int r0 = va ? (gstart + arow) : gstart;
        pA = Ain + (size_t)r0 * K + ach;
    }
    // ---- B loads: row = tid>>3 (0..31), 32B of the 256B row per thread
    int brow = tid >> 3;
    int bch  = (tid & 7) * 16;
    const __half* pB = We + (size_t)brow * NDIM + n0 + bch;

    uint32_t sAd[2], sBd[2];
#pragma unroll
    for (int st = 0; st < 2; st++) {
        sAd[st] = (uint32_t)__cvta_generic_to_shared(&As[st][arow * ASTRIDE + ach]);
        sBd[st] = (uint32_t)__cvta_generic_to_shared(&Bs[st][brow * BSTRIDE + bch]);
    }

    // ---- ldmatrix lane addresses (byte offsets within one stage buffer)
    uint32_t aoff = ((wm * 32 + (lane & 15)) * ASTRIDE + (lane >> 4) * 8) * 2;
    uint32_t boff = (((lane & 7) + ((lane >> 3) & 1) * 8) * BSTRIDE +
                     wn * 64 + (lane >> 4) * 8) * 2;
    uint32_t aBase[2], bBase[2];
#pragma unroll
    for (int st = 0; st < 2; st++) {
        aBase[st] = (uint32_t)__cvta_generic_to_shared(&As[st][0]) + aoff;
        bBase[st] = (uint32_t)__cvta_generic_to_shared(&Bs[st][0]) + boff;
    }

    float acc[2][8][4];
#pragma unroll
    for (int mi = 0; mi < 2; mi++)
#pragma unroll
        for (int ni = 0; ni < 8; ni++)
#pragma unroll
            for (int j = 0; j < 4; j++) acc[mi][ni][j] = 0.f;

    int nsteps = K / BK;

    // prefetch stage 0
    cp16(sAd[0],      pA,     va);
    cp16(sAd[0] + 16, pA + 8, va);
    cp16(sBd[0],      pB,     true);
    cp16(sBd[0] + 16, pB + 8, true);
    asm volatile("cp.async.commit_group;\n" ::: "memory");

    for (int s = 0; s < nsteps; s++) {
        if (s + 1 < nsteps) {
            int st = (s + 1) & 1;
            size_t ka = (size_t)(s + 1) * BK;
            size_t kb = (size_t)(s + 1) * BK * NDIM;
            cp16(sAd[st],      pA + ka,     va);
            cp16(sAd[st] + 16, pA + ka + 8, va);
            cp16(sBd[st],      pB + kb,     true);
            cp16(sBd[st] + 16, pB + kb + 8, true);
            asm volatile("cp.async.commit_group;\n" ::: "memory");
            asm volatile("cp.async.wait_group 1;\n" ::: "memory");
        } else {
            asm volatile("cp.async.wait_group 0;\n" ::: "memory");
        }
        __syncthreads();
        int st = s & 1;
#pragma unroll
        for (int kk = 0; kk < 2; kk++) {
            uint32_t a[2][4];
#pragma unroll
            for (int mi = 0; mi < 2; mi++)
                ldsm4(a[mi][0], a[mi][1], a[mi][2], a[mi][3],
                      aBase[st] + (mi * 16 * ASTRIDE + kk * 16) * 2);
            uint32_t b[8][2];
#pragma unroll
            for (int t = 0; t < 4; t++) {
                uint32_t r0, r1, r2, r3;
                ldsm4t(r0, r1, r2, r3,
                       bBase[st] + (kk * 16 * BSTRIDE + t * 16) * 2);
                b[2 * t][0] = r0; b[2 * t][1] = r1;
                b[2 * t + 1][0] = r2; b[2 * t + 1][1] = r3;
            }
#pragma unroll
            for (int mi = 0; mi < 2; mi++)
#pragma unroll
                for (int ni = 0; ni < 8; ni++) {
                    asm volatile(
                        "mma.sync.aligned.m16n8k16.row.col.f32.f16.f16.f32 "
                        "{%0,%1,%2,%3}, {%4,%5,%6,%7}, {%8,%9}, {%0,%1,%2,%3};\n"
                        : "+f"(acc[mi][ni][0]), "+f"(acc[mi][ni][1]),
                          "+f"(acc[mi][ni][2]), "+f"(acc[mi][ni][3])
                        : "r"(a[mi][0]), "r"(a[mi][1]), "r"(a[mi][2]), "r"(a[mi][3]),
                          "r"(b[ni][0]), "r"(b[ni][1]));
                }
        }
        __syncthreads();
    }

    // ---- epilogue (C frag: rows gid, gid+8; cols tig*2, tig*2+1)
#pragma unroll
    for (int mi = 0; mi < 2; mi++) {
        int rlo = wm * 32 + mi * 16 + gid;
        int rhi = rlo + 8;
        bool vlo = rlo < mcount, vhi = rhi < mcount;
        size_t dlo = 0, dhi = 0;
        float glo = 1.f, ghi = 1.f;
        if (MODE == 0) {
            dlo = (size_t)(gstart + rlo) * NDIM;
            dhi = (size_t)(gstart + rhi) * NDIM;
        } else {
            int tlo = vlo ? g_perm[gstart + rlo] : 0;
            int thi = vhi ? g_perm[gstart + rhi] : 0;
            glo = g_prob[tlo];
            ghi = g_prob[thi];
            dlo = (size_t)tlo * NDIM;
            dhi = (size_t)thi * NDIM;
        }
#pragma unroll
        for (int ni = 0; ni < 8; ni++) {
            int col = n0 + wn * 64 + ni * 8 + tig * 2;
            float bz0 = bias[(size_t)e * NDIM + col];
            float bz1 = bias[(size_t)e * NDIM + col + 1];
            float v00 = acc[mi][ni][0] + bz0, v01 = acc[mi][ni][1] + bz1;
            float v10 = acc[mi][ni][2] + bz0, v11 = acc[mi][ni][3] + bz1;
            if (MODE == 0) {
                if (vlo) *(__half2*)&g_hh[dlo + col] =
                    __floats2half2_rn(gelu_f(v00), gelu_f(v01));
                if (vhi) *(__half2*)&g_hh[dhi + col] =
                    __floats2half2_rn(gelu_f(v10), gelu_f(v11));
            } else {
                if (vlo) *(float2*)&OutG[dlo + col] = make_float2(glo * v00, glo * v01);
                if (vhi) *(float2*)&OutG[dhi + col] = make_float2(ghi * v10, ghi * v11);
            }
        }
    }
}

// ---------------------------------------------------------------- launch
extern "C" void kernel_launch(void* const* d_in, const int* in_sizes, int n_in,
                              void* d_out, int out_size) {
    const float* x  = (const float*)d_in[0];
    const float* Wr = (const float*)d_in[1];
    const float* br = (const float*)d_in[2];
    const float* W1 = (const float*)d_in[3];
    const float* b1 = (const float*)d_in[4];
    const float* W2 = (const float*)d_in[5];
    const float* b2 = (const float*)d_in[6];
    float* out = (float*)d_out;

    __half *xh, *w1h, *w2h, *hh;
    cudaGetSymbolAddress((void**)&xh,  g_xh);
    cudaGetSymbolAddress((void**)&w1h, g_w1h);
    cudaGetSymbolAddress((void**)&w2h, g_w2h);
    cudaGetSymbolAddress((void**)&hh,  g_hh);

    init_k<<<1, 32>>>();
    prep_k<<<ROUTER_BLKS + W1CVT_BLKS + XCVT_BLKS, 256>>>(x, Wr, br, W1, w1h, xh);
    setup_k<<<1, 32>>>(out, out_size);
    scatter_k<<<N_TOK / 256, 256>>>();
    // gemm0: 72 m-tile slots + 9 trailing x-slots (x32 y) = 288 W2-convert CTAs
    moe_gemm_k<0><<<dim3(72 + 9, HDIM / 128), 256>>>(xh, w1h, b1, nullptr,
                                                     W2, w2h, CDIM, HDIM);
    moe_gemm_k<1><<<dim3(72, CDIM / 128), 256>>>(hh, w2h, b2, out,
                                                 nullptr, nullptr, HDIM, CDIM);
}

// round 9
// speedup vs baseline: 1.4394x; 1.4394x over previous
#include <cuda_runtime.h>
#include <cuda_fp16.h>
#include <cstdint>

#define N_TOK 8192
#define CDIM  1024
#define HDIM  4096
#define NEXP  8
#define BM    128
#define BK    32
#define MAXTILES 80
#define ASTRIDE 40    // halves per A smem row (80 B): conflict-free ldsm
#define BSTRIDE 136   // halves per B smem row (272 B): conflict-free ldsm

// ---- scratch (static __device__ — allocation-free per harness rules) ----
__device__ __half g_hh [(size_t)N_TOK * HDIM];           // fc1 act (fp16), sorted order
__device__ __half g_xh [(size_t)N_TOK * CDIM];           // x in fp16
__device__ __half g_w1h[(size_t)NEXP * CDIM * HDIM];     // W1 fp16
__device__ __half g_w2h[(size_t)NEXP * HDIM * CDIM];     // W2 fp16
__device__ int    g_idx[N_TOK];
__device__ float  g_prob[N_TOK];
__device__ int    g_perm[N_TOK];
__device__ int    g_counts[NEXP];
__device__ int    g_cursor[NEXP];
__device__ int    g_offset[NEXP + 1];
__device__ int    g_tileExpert[MAXTILES];
__device__ int    g_tileStart[MAXTILES];
__device__ int    g_tileCount[MAXTILES];
__device__ int    g_numTiles;

// ---------------------------------------------------------------- helpers
__device__ __forceinline__ float gelu_f(float v) {
    return 0.5f * v * (1.0f + erff(v * 0.70710678118654752f));
}
__device__ __forceinline__ void cp16(uint32_t dst, const void* src, bool pred) {
    int sz = pred ? 16 : 0;  // src-size 0 => zero-fill 16B
    asm volatile("cp.async.ca.shared.global [%0], [%1], 16, %2;\n"
                 :: "r"(dst), "l"(src), "r"(sz));
}
__device__ __forceinline__ void ldsm4(uint32_t& r0, uint32_t& r1, uint32_t& r2,
                                      uint32_t& r3, uint32_t addr) {
    asm volatile("ldmatrix.sync.aligned.m8n8.x4.shared.b16 {%0,%1,%2,%3}, [%4];"
                 : "=r"(r0), "=r"(r1), "=r"(r2), "=r"(r3) : "r"(addr));
}
__device__ __forceinline__ void ldsm4t(uint32_t& r0, uint32_t& r1, uint32_t& r2,
                                       uint32_t& r3, uint32_t addr) {
    asm volatile("ldmatrix.sync.aligned.m8n8.x4.trans.shared.b16 {%0,%1,%2,%3}, [%4];"
                 : "=r"(r0), "=r"(r1), "=r"(r2), "=r"(r3) : "r"(addr));
}

// ---------------------------------------------------------------- small kernels
__global__ void init_k() {
    int t = threadIdx.x;
    if (t < NEXP) { g_counts[t] = 0; g_cursor[t] = 0; }
}

__global__ void cvt_h_k(const float* __restrict__ src, __half* __restrict__ dst,
                        int n4) {
    int i = blockIdx.x * blockDim.x + threadIdx.x;
    int stride = gridDim.x * blockDim.x;
    const float4* s = (const float4*)src;
    __half2* d = (__half2*)dst;
    for (; i < n4; i += stride) {
        float4 v = s[i];
        d[2 * i]     = __floats2half2_rn(v.x, v.y);
        d[2 * i + 1] = __floats2half2_rn(v.z, v.w);
    }
}

__global__ void router_k(const float* __restrict__ x, const float* __restrict__ Wr,
                         const float* __restrict__ br) {
    int gt = blockIdx.x * blockDim.x + threadIdx.x;
    int tok = gt >> 5, lane = gt & 31;
    if (tok >= N_TOK) return;
    const float* xr = x + (size_t)tok * CDIM;
    float s[NEXP];
#pragma unroll
    for (int e = 0; e < NEXP; e++) s[e] = 0.f;
    for (int k = lane; k < CDIM; k += 32) {
        float xv = xr[k];
        const float4* w = (const float4*)(Wr + (size_t)k * NEXP);
        float4 w0 = w[0], w1 = w[1];
        s[0] += xv * w0.x; s[1] += xv * w0.y; s[2] += xv * w0.z; s[3] += xv * w0.w;
        s[4] += xv * w1.x; s[5] += xv * w1.y; s[6] += xv * w1.z; s[7] += xv * w1.w;
    }
#pragma unroll
    for (int e = 0; e < NEXP; e++)
#pragma unroll
        for (int o = 16; o > 0; o >>= 1) s[e] += __shfl_xor_sync(0xffffffffu, s[e], o);
    if (lane == 0) {
        float l[NEXP];
        l[0] = s[0] + br[0];
        float m = l[0]; int mi = 0;
#pragma unroll
        for (int e = 1; e < NEXP; e++) {
            l[e] = s[e] + br[e];
            if (l[e] > m) { m = l[e]; mi = e; }
        }
        float sum = 0.f;
#pragma unroll
        for (int e = 0; e < NEXP; e++) sum += expf(l[e] - m);
        g_prob[tok] = 1.0f / sum;
        g_idx[tok] = mi;
        atomicAdd(&g_counts[mi], 1);
    }
}

__global__ void setup_k(float* out, int out_size) {
    if (threadIdx.x != 0 || blockIdx.x != 0) return;
    int off = 0, nt = 0;
    for (int e = 0; e < NEXP; e++) {
        g_offset[e] = off;
        int c = g_counts[e];
        int t = (c + BM - 1) / BM;
        for (int i = 0; i < t; i++) {
            g_tileExpert[nt] = e;
            g_tileStart[nt] = off + i * BM;
            int rem = c - i * BM;
            g_tileCount[nt] = rem < BM ? rem : BM;
            nt++;
        }
        off += c;
    }
    g_offset[NEXP] = off;
    g_numTiles = nt;
    float aux = 0.f, tot = (float)off;
    if (tot < 1.f) tot = 1.f;
    for (int e = 0; e < NEXP; e++) {
        float d = (float)g_counts[e] / tot - 1.0f / NEXP;
        aux += d * d;
    }
    aux *= 1.0f / NEXP;
    if (out_size > N_TOK * CDIM) out[(size_t)N_TOK * CDIM] = aux;
}

__global__ void scatter_k() {
    int t = blockIdx.x * blockDim.x + threadIdx.x;
    if (t >= N_TOK) return;
    int e = g_idx[t];
    int p = atomicAdd(&g_cursor[e], 1);
    g_perm[g_offset[e] + p] = t;
}

// ---------------------------------------------------------------- fp16 grouped GEMM
// 8 warps = 4(M) x 2(N); warp tile 32 x 64; CTA tile 128 x 128, BK=32 halves.
// __launch_bounds__(256, 2): cap regs at 128 -> 2 CTAs/SM so one CTA's MMA
// phase hides the other's barrier/epilogue bubbles.
// MODE 0: g_hh = fp16(gelu(g_xh[perm] @ W1[e] + b1[e]))  K=1024, NDIM=4096
// MODE 1: out[token] = prob * (g_hh @ W2[e] + b2[e])     K=4096, NDIM=1024
template <int MODE>
__global__ void __launch_bounds__(256, 2)
moe_gemm_k(const __half* __restrict__ Ain, const __half* __restrict__ W,
           const float* __restrict__ bias, float* __restrict__ OutG,
           int K, int NDIM) {
    __shared__ __half As[2][BM * ASTRIDE];
    __shared__ __half Bs[2][BK * BSTRIDE];

    int mt = blockIdx.x;
    if (mt >= g_numTiles) return;
    int e      = g_tileExpert[mt];
    int gstart = g_tileStart[mt];
    int mcount = g_tileCount[mt];
    int n0     = blockIdx.y * 128;

    const __half* We = W + (size_t)e * K * NDIM;

    int tid = threadIdx.x, lane = tid & 31, warp = tid >> 5;
    int wm = warp & 3;        // 4 warps along M (32 rows)
    int wn = warp >> 2;       // 2 warps along N (64 cols)
    int gid = lane >> 2, tig = lane & 3;

    // ---- A loads: row = tid>>1, 32B of the 64B row per thread (2 x cp16)
    int arow = tid >> 1;
    int ach  = (tid & 1) * 16;
    bool va  = arow < mcount;
    const __half* pA;
    if (MODE == 0) {
        int t0 = va ? g_perm[gstart + arow] : g_perm[gstart];
        pA = Ain + (size_t)t0 * K + ach;
    } else {
        int r0 = va ? (gstart + arow) : gstart;
        pA = Ain + (size_t)r0 * K + ach;
    }
    // ---- B loads: row = tid>>3 (0..31), 32B of the 256B row per thread
    int brow = tid >> 3;
    int bch  = (tid & 7) * 16;
    const __half* pB = We + (size_t)brow * NDIM + n0 + bch;

    uint32_t sAd[2], sBd[2];
#pragma unroll
    for (int st = 0; st < 2; st++) {
        sAd[st] = (uint32_t)__cvta_generic_to_shared(&As[st][arow * ASTRIDE + ach]);
        sBd[st] = (uint32_t)__cvta_generic_to_shared(&Bs[st][brow * BSTRIDE + bch]);
    }

    // ---- ldmatrix lane addresses (byte offsets within one stage buffer)
    uint32_t aoff = ((wm * 32 + (lane & 15)) * ASTRIDE + (lane >> 4) * 8) * 2;
    uint32_t boff = (((lane & 7) + ((lane >> 3) & 1) * 8) * BSTRIDE +
                     wn * 64 + (lane >> 4) * 8) * 2;
    uint32_t aBase[2], bBase[2];
#pragma unroll
    for (int st = 0; st < 2; st++) {
        aBase[st] = (uint32_t)__cvta_generic_to_shared(&As[st][0]) + aoff;
        bBase[st] = (uint32_t)__cvta_generic_to_shared(&Bs[st][0]) + boff;
    }

    float acc[2][8][4];
#pragma unroll
    for (int mi = 0; mi < 2; mi++)
#pragma unroll
        for (int ni = 0; ni < 8; ni++)
#pragma unroll
            for (int j = 0; j < 4; j++) acc[mi][ni][j] = 0.f;

    int nsteps = K / BK;

    // prefetch stage 0
    cp16(sAd[0],      pA,     va);
    cp16(sAd[0] + 16, pA + 8, va);
    cp16(sBd[0],      pB,     true);
    cp16(sBd[0] + 16, pB + 8, true);
    asm volatile("cp.async.commit_group;\n" ::: "memory");

    for (int s = 0; s < nsteps; s++) {
        if (s + 1 < nsteps) {
            int st = (s + 1) & 1;
            size_t ka = (size_t)(s + 1) * BK;
            size_t kb = (size_t)(s + 1) * BK * NDIM;
            cp16(sAd[st],      pA + ka,     va);
            cp16(sAd[st] + 16, pA + ka + 8, va);
            cp16(sBd[st],      pB + kb,     true);
            cp16(sBd[st] + 16, pB + kb + 8, true);
            asm volatile("cp.async.commit_group;\n" ::: "memory");
            asm volatile("cp.async.wait_group 1;\n" ::: "memory");
        } else {
            asm volatile("cp.async.wait_group 0;\n" ::: "memory");
        }
        __syncthreads();
        int st = s & 1;
#pragma unroll
        for (int kk = 0; kk < 2; kk++) {
            uint32_t a[2][4];
#pragma unroll
            for (int mi = 0; mi < 2; mi++)
                ldsm4(a[mi][0], a[mi][1], a[mi][2], a[mi][3],
                      aBase[st] + (mi * 16 * ASTRIDE + kk * 16) * 2);
            uint32_t b[8][2];
#pragma unroll
            for (int t = 0; t < 4; t++) {
                uint32_t r0, r1, r2, r3;
                ldsm4t(r0, r1, r2, r3,
                       bBase[st] + (kk * 16 * BSTRIDE + t * 16) * 2);
                b[2 * t][0] = r0; b[2 * t][1] = r1;
                b[2 * t + 1][0] = r2; b[2 * t + 1][1] = r3;
            }
#pragma unroll
            for (int mi = 0; mi < 2; mi++)
#pragma unroll
                for (int ni = 0; ni < 8; ni++) {
                    asm volatile(
                        "mma.sync.aligned.m16n8k16.row.col.f32.f16.f16.f32 "
                        "{%0,%1,%2,%3}, {%4,%5,%6,%7}, {%8,%9}, {%0,%1,%2,%3};\n"
                        : "+f"(acc[mi][ni][0]), "+f"(acc[mi][ni][1]),
                          "+f"(acc[mi][ni][2]), "+f"(acc[mi][ni][3])
                        : "r"(a[mi][0]), "r"(a[mi][1]), "r"(a[mi][2]), "r"(a[mi][3]),
                          "r"(b[ni][0]), "r"(b[ni][1]));
                }
        }
        __syncthreads();
    }

    // ---- epilogue (C frag: rows gid, gid+8; cols tig*2, tig*2+1)
#pragma unroll
    for (int mi = 0; mi < 2; mi++) {
        int rlo = wm * 32 + mi * 16 + gid;
        int rhi = rlo + 8;
        bool vlo = rlo < mcount, vhi = rhi < mcount;
        size_t dlo = 0, dhi = 0;
        float glo = 1.f, ghi = 1.f;
        if (MODE == 0) {
            dlo = (size_t)(gstart + rlo) * NDIM;
            dhi = (size_t)(gstart + rhi) * NDIM;
        } else {
            int tlo = vlo ? g_perm[gstart + rlo] : 0;
            int thi = vhi ? g_perm[gstart + rhi] : 0;
            glo = g_prob[tlo];
            ghi = g_prob[thi];
            dlo = (size_t)tlo * NDIM;
            dhi = (size_t)thi * NDIM;
        }
#pragma unroll
        for (int ni = 0; ni < 8; ni++) {
            int col = n0 + wn * 64 + ni * 8 + tig * 2;
            float bz0 = bias[(size_t)e * NDIM + col];
            float bz1 = bias[(size_t)e * NDIM + col + 1];
            float v00 = acc[mi][ni][0] + bz0, v01 = acc[mi][ni][1] + bz1;
            float v10 = acc[mi][ni][2] + bz0, v11 = acc[mi][ni][3] + bz1;
            if (MODE == 0) {
                if (vlo) *(__half2*)&g_hh[dlo + col] =
                    __floats2half2_rn(gelu_f(v00), gelu_f(v01));
                if (vhi) *(__half2*)&g_hh[dhi + col] =
                    __floats2half2_rn(gelu_f(v10), gelu_f(v11));
            } else {
                if (vlo) *(float2*)&OutG[dlo + col] = make_float2(glo * v00, glo * v01);
                if (vhi) *(float2*)&OutG[dhi + col] = make_float2(ghi * v10, ghi * v11);
            }
        }
    }
}

// ---------------------------------------------------------------- launch
extern "C" void kernel_launch(void* const* d_in, const int* in_sizes, int n_in,
                              void* d_out, int out_size) {
    const float* x  = (const float*)d_in[0];
    const float* Wr = (const float*)d_in[1];
    const float* br = (const float*)d_in[2];
    const float* W1 = (const float*)d_in[3];
    const float* b1 = (const float*)d_in[4];
    const float* W2 = (const float*)d_in[5];
    const float* b2 = (const float*)d_in[6];
    float* out = (float*)d_out;

    __half *xh, *w1h, *w2h, *hh;
    cudaGetSymbolAddress((void**)&xh,  g_xh);
    cudaGetSymbolAddress((void**)&w1h, g_w1h);
    cudaGetSymbolAddress((void**)&w2h, g_w2h);
    cudaGetSymbolAddress((void**)&hh,  g_hh);

    init_k<<<1, 32>>>();
    router_k<<<N_TOK * 32 / 256, 256>>>(x, Wr, br);
    cvt_h_k<<<2048, 256>>>(x,  xh,  N_TOK * CDIM / 4);
    cvt_h_k<<<8192, 256>>>(W1, w1h, NEXP * CDIM * HDIM / 4);
    cvt_h_k<<<8192, 256>>>(W2, w2h, NEXP * HDIM * CDIM / 4);
    setup_k<<<1, 32>>>(out, out_size);
    scatter_k<<<N_TOK / 256, 256>>>();
    // grid.x = m-tile slot (<=71 used), grid.y = n-block; x-fastest keeps one
    // weight column-block resident in L2 across all concurrent m-tiles.
    moe_gemm_k<0><<<dim3(72, HDIM / 128), 256>>>(xh, w1h, b1, nullptr, CDIM, HDIM);
    moe_gemm_k<1><<<dim3(72, CDIM / 128), 256>>>(hh, w2h, b2, out,     HDIM, CDIM);
}

// round 10
// speedup vs baseline: 1.4400x; 1.0004x over previous
#include <cuda_runtime.h>
#include <cuda_fp16.h>
#include <cstdint>

#define N_TOK 8192
#define CDIM  1024
#define HDIM  4096
#define NEXP  8
#define BM    128
#define BK    32
#define MAXTILES 80
#define ASTRIDE 40    // halves per A smem row (80 B): conflict-free ldsm
#define BSTRIDE 136   // halves per B smem row (272 B): conflict-free ldsm
#define W_N4 (NEXP * CDIM * HDIM / 4)   // float4 count per weight tensor

// ---- scratch (static __device__ — allocation-free per harness rules) ----
__device__ __half g_hh [(size_t)N_TOK * HDIM];           // fc1 act (fp16), sorted order
__device__ __half g_xh [(size_t)N_TOK * CDIM];           // x in fp16
__device__ __half g_w1h[(size_t)NEXP * CDIM * HDIM];     // W1 fp16
__device__ __half g_w2h[(size_t)NEXP * HDIM * CDIM];     // W2 fp16
__device__ int    g_idx[N_TOK];
__device__ float  g_prob[N_TOK];
__device__ int    g_perm[N_TOK];
__device__ int    g_counts[NEXP];
__device__ int    g_cursor[NEXP];
__device__ int    g_offset[NEXP + 1];
__device__ int    g_tileExpert[MAXTILES];
__device__ int    g_tileStart[MAXTILES];
__device__ int    g_tileCount[MAXTILES];
__device__ int    g_numTiles;

// ---------------------------------------------------------------- helpers
__device__ __forceinline__ float gelu_f(float v) {
    return 0.5f * v * (1.0f + erff(v * 0.70710678118654752f));
}
__device__ __forceinline__ void cp16(uint32_t dst, const void* src, bool pred) {
    int sz = pred ? 16 : 0;  // src-size 0 => zero-fill 16B
    asm volatile("cp.async.ca.shared.global [%0], [%1], 16, %2;\n"
                 :: "r"(dst), "l"(src), "r"(sz));
}
__device__ __forceinline__ void ldsm4(uint32_t& r0, uint32_t& r1, uint32_t& r2,
                                      uint32_t& r3, uint32_t addr) {
    asm volatile("ldmatrix.sync.aligned.m8n8.x4.shared.b16 {%0,%1,%2,%3}, [%4];"
                 : "=r"(r0), "=r"(r1), "=r"(r2), "=r"(r3) : "r"(addr));
}
__device__ __forceinline__ void ldsm4t(uint32_t& r0, uint32_t& r1, uint32_t& r2,
                                       uint32_t& r3, uint32_t addr) {
    asm volatile("ldmatrix.sync.aligned.m8n8.x4.trans.shared.b16 {%0,%1,%2,%3}, [%4];"
                 : "=r"(r0), "=r"(r1), "=r"(r2), "=r"(r3) : "r"(addr));
}

// ---------------------------------------------------------------- small kernels
__global__ void init_k() {
    int t = threadIdx.x;
    if (t < NEXP) { g_counts[t] = 0; g_cursor[t] = 0; }
}

// both weight tensors fp32->fp16 in one launch: blocks [0,8192)->W1, [8192,..)->W2
__global__ void cvt_w_k(const float* __restrict__ W1, __half* __restrict__ w1h,
                        const float* __restrict__ W2, __half* __restrict__ w2h) {
    int half_blocks = gridDim.x >> 1;
    const float4* s;
    __half2* d;
    int b = blockIdx.x;
    if (b < half_blocks) {
        s = (const float4*)W1; d = (__half2*)w1h;
    } else {
        s = (const float4*)W2; d = (__half2*)w2h;
        b -= half_blocks;
    }
    int stride = half_blocks * blockDim.x;
    for (int i = b * blockDim.x + threadIdx.x; i < W_N4; i += stride) {
        float4 v = s[i];
        d[2 * i]     = __floats2half2_rn(v.x, v.y);
        d[2 * i + 1] = __floats2half2_rn(v.z, v.w);
    }
}

// router + fused x->fp16 conversion (x is read exactly once).
// one warp per token; float4 loads; Wr (32KB) stays L1-resident.
__global__ void router_k(const float* __restrict__ x, const float* __restrict__ Wr,
                         const float* __restrict__ br, __half* __restrict__ xh) {
    int gt = blockIdx.x * blockDim.x + threadIdx.x;
    int tok = gt >> 5, lane = gt & 31;
    if (tok >= N_TOK) return;
    const float* xr = x + (size_t)tok * CDIM;
    __half2* xo = (__half2*)(xh + (size_t)tok * CDIM);
    float s[NEXP];
#pragma unroll
    for (int e = 0; e < NEXP; e++) s[e] = 0.f;
#pragma unroll
    for (int it = 0; it < CDIM / 128; it++) {
        int k = it * 128 + lane * 4;
        float4 xv = *(const float4*)(xr + k);
        const float4* w0 = (const float4*)(Wr + (size_t)k * NEXP);
#pragma unroll
        for (int c = 0; c < 4; c++) {
            float xc = (&xv.x)[c];
            float4 wa = w0[2 * c], wb = w0[2 * c + 1];
            s[0] += xc * wa.x; s[1] += xc * wa.y; s[2] += xc * wa.z; s[3] += xc * wa.w;
            s[4] += xc * wb.x; s[5] += xc * wb.y; s[6] += xc * wb.z; s[7] += xc * wb.w;
        }
        xo[k / 2]     = __floats2half2_rn(xv.x, xv.y);
        xo[k / 2 + 1] = __floats2half2_rn(xv.z, xv.w);
    }
#pragma unroll
    for (int e = 0; e < NEXP; e++)
#pragma unroll
        for (int o = 16; o > 0; o >>= 1) s[e] += __shfl_xor_sync(0xffffffffu, s[e], o);
    if (lane == 0) {
        float l[NEXP];
        l[0] = s[0] + br[0];
        float m = l[0]; int mi = 0;
#pragma unroll
        for (int e = 1; e < NEXP; e++) {
            l[e] = s[e] + br[e];
            if (l[e] > m) { m = l[e]; mi = e; }
        }
        float sum = 0.f;
#pragma unroll
        for (int e = 0; e < NEXP; e++) sum += expf(l[e] - m);
        g_prob[tok] = 1.0f / sum;
        g_idx[tok] = mi;
        atomicAdd(&g_counts[mi], 1);
    }
}

__global__ void setup_k(float* out, int out_size) {
    if (threadIdx.x != 0 || blockIdx.x != 0) return;
    int off = 0, nt = 0;
    for (int e = 0; e < NEXP; e++) {
        g_offset[e] = off;
        int c = g_counts[e];
        int t = (c + BM - 1) / BM;
        for (int i = 0; i < t; i++) {
            g_tileExpert[nt] = e;
            g_tileStart[nt] = off + i * BM;
            int rem = c - i * BM;
            g_tileCount[nt] = rem < BM ? rem : BM;
            nt++;
        }
        off += c;
    }
    g_offset[NEXP] = off;
    g_numTiles = nt;
    float aux = 0.f, tot = (float)off;
    if (tot < 1.f) tot = 1.f;
    for (int e = 0; e < NEXP; e++) {
        float d = (float)g_counts[e] / tot - 1.0f / NEXP;
        aux += d * d;
    }
    aux *= 1.0f / NEXP;
    if (out_size > N_TOK * CDIM) out[(size_t)N_TOK * CDIM] = aux;
}

__global__ void scatter_k() {
    int t = blockIdx.x * blockDim.x + threadIdx.x;
    if (t >= N_TOK) return;
    int e = g_idx[t];
    int p = atomicAdd(&g_cursor[e], 1);
    g_perm[g_offset[e] + p] = t;
}

// ---------------------------------------------------------------- fp16 grouped GEMM
// 8 warps = 4(M) x 2(N); warp tile 32 x 64; CTA tile 128 x 128, BK=32 halves.
// MODE 0: g_hh = fp16(gelu(g_xh[perm] @ W1[e] + b1[e]))  K=1024, NDIM=4096
// MODE 1: out[token] = prob * (g_hh @ W2[e] + b2[e])     K=4096, NDIM=1024
template <int MODE>
__global__ void __launch_bounds__(256)
moe_gemm_k(const __half* __restrict__ Ain, const __half* __restrict__ W,
           const float* __restrict__ bias, float* __restrict__ OutG,
           int K, int NDIM) {
    __shared__ __half As[2][BM * ASTRIDE];
    __shared__ __half Bs[2][BK * BSTRIDE];

    int mt = blockIdx.x;
    if (mt >= g_numTiles) return;
    int e      = g_tileExpert[mt];
    int gstart = g_tileStart[mt];
    int mcount = g_tileCount[mt];
    int n0     = blockIdx.y * 128;

    const __half* We = W + (size_t)e * K * NDIM;

    int tid = threadIdx.x, lane = tid & 31, warp = tid >> 5;
    int wm = warp & 3;        // 4 warps along M (32 rows)
    int wn = warp >> 2;       // 2 warps along N (64 cols)
    int gid = lane >> 2, tig = lane & 3;

    // ---- A loads: row = tid>>1, 32B of the 64B row per thread (2 x cp16)
    int arow = tid >> 1;
    int ach  = (tid & 1) * 16;
    bool va  = arow < mcount;
    const __half* pA;
    if (MODE == 0) {
        int t0 = va ? g_perm[gstart + arow] : g_perm[gstart];
        pA = Ain + (size_t)t0 * K + ach;
    } else {
        int r0 = va ? (gstart + arow) : gstart;
        pA = Ain + (size_t)r0 * K + ach;
    }
    // ---- B loads: row = tid>>3 (0..31), 32B of the 256B row per thread
    int brow = tid >> 3;
    int bch  = (tid & 7) * 16;
    const __half* pB = We + (size_t)brow * NDIM + n0 + bch;

    uint32_t sAd[2], sBd[2];
#pragma unroll
    for (int st = 0; st < 2; st++) {
        sAd[st] = (uint32_t)__cvta_generic_to_shared(&As[st][arow * ASTRIDE + ach]);
        sBd[st] = (uint32_t)__cvta_generic_to_shared(&Bs[st][brow * BSTRIDE + bch]);
    }

    // ---- ldmatrix lane addresses (byte offsets within one stage buffer)
    uint32_t aoff = ((wm * 32 + (lane & 15)) * ASTRIDE + (lane >> 4) * 8) * 2;
    uint32_t boff = (((lane & 7) + ((lane >> 3) & 1) * 8) * BSTRIDE +
                     wn * 64 + (lane >> 4) * 8) * 2;
    uint32_t aBase[2], bBase[2];
#pragma unroll
    for (int st = 0; st < 2; st++) {
        aBase[st] = (uint32_t)__cvta_generic_to_shared(&As[st][0]) + aoff;
        bBase[st] = (uint32_t)__cvta_generic_to_shared(&Bs[st][0]) + boff;
    }

    float acc[2][8][4];
#pragma unroll
    for (int mi = 0; mi < 2; mi++)
#pragma unroll
        for (int ni = 0; ni < 8; ni++)
#pragma unroll
            for (int j = 0; j < 4; j++) acc[mi][ni][j] = 0.f;

    int nsteps = K / BK;

    // prefetch stage 0
    cp16(sAd[0],      pA,     va);
    cp16(sAd[0] + 16, pA + 8, va);
    cp16(sBd[0],      pB,     true);
    cp16(sBd[0] + 16, pB + 8, true);
    asm volatile("cp.async.commit_group;\n" ::: "memory");

    for (int s = 0; s < nsteps; s++) {
        if (s + 1 < nsteps) {
            int st = (s + 1) & 1;
            size_t ka = (size_t)(s + 1) * BK;
            size_t kb = (size_t)(s + 1) * BK * NDIM;
            cp16(sAd[st],      pA + ka,     va);
            cp16(sAd[st] + 16, pA + ka + 8, va);
            cp16(sBd[st],      pB + kb,     true);
            cp16(sBd[st] + 16, pB + kb + 8, true);
            asm volatile("cp.async.commit_group;\n" ::: "memory");
            asm volatile("cp.async.wait_group 1;\n" ::: "memory");
        } else {
            asm volatile("cp.async.wait_group 0;\n" ::: "memory");
        }
        __syncthreads();
        int st = s & 1;
#pragma unroll
        for (int kk = 0; kk < 2; kk++) {
            uint32_t a[2][4];
#pragma unroll
            for (int mi = 0; mi < 2; mi++)
                ldsm4(a[mi][0], a[mi][1], a[mi][2], a[mi][3],
                      aBase[st] + (mi * 16 * ASTRIDE + kk * 16) * 2);
            uint32_t b[8][2];
#pragma unroll
            for (int t = 0; t < 4; t++) {
                uint32_t r0, r1, r2, r3;
                ldsm4t(r0, r1, r2, r3,
                       bBase[st] + (kk * 16 * BSTRIDE + t * 16) * 2);
                b[2 * t][0] = r0; b[2 * t][1] = r1;
                b[2 * t + 1][0] = r2; b[2 * t + 1][1] = r3;
            }
#pragma unroll
            for (int mi = 0; mi < 2; mi++)
#pragma unroll
                for (int ni = 0; ni < 8; ni++) {
                    asm volatile(
                        "mma.sync.aligned.m16n8k16.row.col.f32.f16.f16.f32 "
                        "{%0,%1,%2,%3}, {%4,%5,%6,%7}, {%8,%9}, {%0,%1,%2,%3};\n"
                        : "+f"(acc[mi][ni][0]), "+f"(acc[mi][ni][1]),
                          "+f"(acc[mi][ni][2]), "+f"(acc[mi][ni][3])
                        : "r"(a[mi][0]), "r"(a[mi][1]), "r"(a[mi][2]), "r"(a[mi][3]),
                          "r"(b[ni][0]), "r"(b[ni][1]));
                }
        }
        __syncthreads();
    }

    // ---- epilogue (C frag: rows gid, gid+8; cols tig*2, tig*2+1)
#pragma unroll
    for (int mi = 0; mi < 2; mi++) {
        int rlo = wm * 32 + mi * 16 + gid;
        int rhi = rlo + 8;
        bool vlo = rlo < mcount, vhi = rhi < mcount;
        size_t dlo = 0, dhi = 0;
        float glo = 1.f, ghi = 1.f;
        if (MODE == 0) {
            dlo = (size_t)(gstart + rlo) * NDIM;
            dhi = (size_t)(gstart + rhi) * NDIM;
        } else {
            int tlo = vlo ? g_perm[gstart + rlo] : 0;
            int thi = vhi ? g_perm[gstart + rhi] : 0;
            glo = g_prob[tlo];
            ghi = g_prob[thi];
            dlo = (size_t)tlo * NDIM;
            dhi = (size_t)thi * NDIM;
        }
#pragma unroll
        for (int ni = 0; ni < 8; ni++) {
            int col = n0 + wn * 64 + ni * 8 + tig * 2;
            float bz0 = bias[(size_t)e * NDIM + col];
            float bz1 = bias[(size_t)e * NDIM + col + 1];
            float v00 = acc[mi][ni][0] + bz0, v01 = acc[mi][ni][1] + bz1;
            float v10 = acc[mi][ni][2] + bz0, v11 = acc[mi][ni][3] + bz1;
            if (MODE == 0) {
                if (vlo) *(__half2*)&g_hh[dlo + col] =
                    __floats2half2_rn(gelu_f(v00), gelu_f(v01));
                if (vhi) *(__half2*)&g_hh[dhi + col] =
                    __floats2half2_rn(gelu_f(v10), gelu_f(v11));
            } else {
                if (vlo) *(float2*)&OutG[dlo + col] = make_float2(glo * v00, glo * v01);
                if (vhi) *(float2*)&OutG[dhi + col] = make_float2(ghi * v10, ghi * v11);
            }
        }
    }
}

// ---------------------------------------------------------------- launch
extern "C" void kernel_launch(void* const* d_in, const int* in_sizes, int n_in,
                              void* d_out, int out_size) {
    const float* x  = (const float*)d_in[0];
    const float* Wr = (const float*)d_in[1];
    const float* br = (const float*)d_in[2];
    const float* W1 = (const float*)d_in[3];
    const float* b1 = (const float*)d_in[4];
    const float* W2 = (const float*)d_in[5];
    const float* b2 = (const float*)d_in[6];
    float* out = (float*)d_out;

    __half *xh, *w1h, *w2h, *hh;
    cudaGetSymbolAddress((void**)&xh,  g_xh);
    cudaGetSymbolAddress((void**)&w1h, g_w1h);
    cudaGetSymbolAddress((void**)&w2h, g_w2h);
    cudaGetSymbolAddress((void**)&hh,  g_hh);

    init_k<<<1, 32>>>();
    router_k<<<N_TOK * 32 / 256, 256>>>(x, Wr, br, xh);
    cvt_w_k<<<16384, 256>>>(W1, w1h, W2, w2h);
    setup_k<<<1, 32>>>(out, out_size);
    scatter_k<<<N_TOK / 256, 256>>>();
    // grid.x = m-tile slot (<=71 used), grid.y = n-block; x-fastest keeps one
    // weight column-block resident in L2 across all concurrent m-tiles.
    moe_gemm_k<0><<<dim3(72, HDIM / 128), 256>>>(xh, w1h, b1, nullptr, CDIM, HDIM);
    moe_gemm_k<1><<<dim3(72, CDIM / 128), 256>>>(hh, w2h, b2, out,     HDIM, CDIM);
}

// round 11
// speedup vs baseline: 1.5196x; 1.0553x over previous
#include <cuda_runtime.h>
#include <cuda_fp16.h>
#include <cstdint>

#define N_TOK 8192
#define CDIM  1024
#define HDIM  4096
#define NEXP  8
#define BM    128
#define BK    32
#define MAXTILES 80
#define ASTRIDE 40    // halves per A smem row (80 B): conflict-free ldsm
#define BSTRIDE 136   // halves per B smem row (272 B): conflict-free ldsm
#define W_N4 (NEXP * CDIM * HDIM / 4)   // float4 count per weight tensor

// ---- scratch (static __device__ — allocation-free per harness rules) ----
__device__ __half g_hh [(size_t)N_TOK * HDIM];           // fc1 act (fp16), sorted order
__device__ __half g_xh [(size_t)N_TOK * CDIM];           // x in fp16
__device__ __half g_w1h[(size_t)NEXP * CDIM * HDIM];     // W1 fp16
__device__ __half g_w2h[(size_t)NEXP * HDIM * CDIM];     // W2 fp16
__device__ int    g_idx[N_TOK];
__device__ float  g_prob[N_TOK];
__device__ int    g_perm[N_TOK];
__device__ int    g_cursor[NEXP];
__device__ int    g_offset[NEXP + 1];
__device__ int    g_tileExpert[MAXTILES];
__device__ int    g_tileStart[MAXTILES];
__device__ int    g_tileCount[MAXTILES];
__device__ int    g_numTiles;

// ---------------------------------------------------------------- helpers
__device__ __forceinline__ float gelu_f(float v) {
    return 0.5f * v * (1.0f + erff(v * 0.70710678118654752f));
}
__device__ __forceinline__ void cp16(uint32_t dst, const void* src, bool pred) {
    int sz = pred ? 16 : 0;  // src-size 0 => zero-fill 16B
    asm volatile("cp.async.ca.shared.global [%0], [%1], 16, %2;\n"
                 :: "r"(dst), "l"(src), "r"(sz));
}
__device__ __forceinline__ void ldsm4(uint32_t& r0, uint32_t& r1, uint32_t& r2,
                                      uint32_t& r3, uint32_t addr) {
    asm volatile("ldmatrix.sync.aligned.m8n8.x4.shared.b16 {%0,%1,%2,%3}, [%4];"
                 : "=r"(r0), "=r"(r1), "=r"(r2), "=r"(r3) : "r"(addr));
}
__device__ __forceinline__ void ldsm4t(uint32_t& r0, uint32_t& r1, uint32_t& r2,
                                       uint32_t& r3, uint32_t addr) {
    asm volatile("ldmatrix.sync.aligned.m8n8.x4.trans.shared.b16 {%0,%1,%2,%3}, [%4];"
                 : "=r"(r0), "=r"(r1), "=r"(r2), "=r"(r3) : "r"(addr));
}

// ---------------------------------------------------------------- small kernels
// x fp32 -> fp16 (identical to R5's cvt_h_k)
__global__ void cvt_h_k(const float* __restrict__ src, __half* __restrict__ dst,
                        int n4) {
    int i = blockIdx.x * blockDim.x + threadIdx.x;
    int stride = gridDim.x * blockDim.x;
    const float4* s = (const float4*)src;
    __half2* d = (__half2*)dst;
    for (; i < n4; i += stride) {
        float4 v = s[i];
        d[2 * i]     = __floats2half2_rn(v.x, v.y);
        d[2 * i + 1] = __floats2half2_rn(v.z, v.w);
    }
}

// both weight tensors fp32->fp16 in one launch: first half of blocks -> W1
__global__ void cvt_w_k(const float* __restrict__ W1, __half* __restrict__ w1h,
                        const float* __restrict__ W2, __half* __restrict__ w2h) {
    int half_blocks = gridDim.x >> 1;
    const float4* s;
    __half2* d;
    int b = blockIdx.x;
    if (b < half_blocks) {
        s = (const float4*)W1; d = (__half2*)w1h;
    } else {
        s = (const float4*)W2; d = (__half2*)w2h;
        b -= half_blocks;
    }
    int stride = half_blocks * blockDim.x;
    for (int i = b * blockDim.x + threadIdx.x; i < W_N4; i += stride) {
        float4 v = s[i];
        d[2 * i]     = __floats2half2_rn(v.x, v.y);
        d[2 * i + 1] = __floats2half2_rn(v.z, v.w);
    }
}

// router (R5 body, minus the count atomics): one warp per token
__global__ void router_k(const float* __restrict__ x, const float* __restrict__ Wr,
                         const float* __restrict__ br) {
    int gt = blockIdx.x * blockDim.x + threadIdx.x;
    int tok = gt >> 5, lane = gt & 31;
    if (tok >= N_TOK) return;
    const float* xr = x + (size_t)tok * CDIM;
    float s[NEXP];
#pragma unroll
    for (int e = 0; e < NEXP; e++) s[e] = 0.f;
    for (int k = lane; k < CDIM; k += 32) {
        float xv = xr[k];
        const float4* w = (const float4*)(Wr + (size_t)k * NEXP);
        float4 w0 = w[0], w1 = w[1];
        s[0] += xv * w0.x; s[1] += xv * w0.y; s[2] += xv * w0.z; s[3] += xv * w0.w;
        s[4] += xv * w1.x; s[5] += xv * w1.y; s[6] += xv * w1.z; s[7] += xv * w1.w;
    }
#pragma unroll
    for (int e = 0; e < NEXP; e++)
#pragma unroll
        for (int o = 16; o > 0; o >>= 1) s[e] += __shfl_xor_sync(0xffffffffu, s[e], o);
    if (lane == 0) {
        float l[NEXP];
        l[0] = s[0] + br[0];
        float m = l[0]; int mi = 0;
#pragma unroll
        for (int e = 1; e < NEXP; e++) {
            l[e] = s[e] + br[e];
            if (l[e] > m) { m = l[e]; mi = e; }
        }
        float sum = 0.f;
#pragma unroll
        for (int e = 0; e < NEXP; e++) sum += expf(l[e] - m);
        g_prob[tok] = 1.0f / sum;
        g_idx[tok] = mi;
    }
}

// setup: count assignments from g_idx (smem atomics), build tile table,
// zero scatter cursors, write aux loss. One block, 256 threads.
__global__ void setup_k(float* out, int out_size) {
    __shared__ int cnt[NEXP];
    int tid = threadIdx.x;
    if (tid < NEXP) cnt[tid] = 0;
    __syncthreads();
    for (int i = tid; i < N_TOK; i += blockDim.x)
        atomicAdd(&cnt[g_idx[i]], 1);
    __syncthreads();
    if (tid == 0) {
        int off = 0, nt = 0;
        for (int e = 0; e < NEXP; e++) {
            g_offset[e] = off;
            g_cursor[e] = 0;
            int c = cnt[e];
            int t = (c + BM - 1) / BM;
            for (int i = 0; i < t; i++) {
                g_tileExpert[nt] = e;
                g_tileStart[nt] = off + i * BM;
                int rem = c - i * BM;
                g_tileCount[nt] = rem < BM ? rem : BM;
                nt++;
            }
            off += c;
        }
        g_offset[NEXP] = off;
        g_numTiles = nt;
        float aux = 0.f, tot = (float)off;
        if (tot < 1.f) tot = 1.f;
        for (int e = 0; e < NEXP; e++) {
            float d = (float)cnt[e] / tot - 1.0f / NEXP;
            aux += d * d;
        }
        aux *= 1.0f / NEXP;
        if (out_size > N_TOK * CDIM) out[(size_t)N_TOK * CDIM] = aux;
    }
}

__global__ void scatter_k() {
    int t = blockIdx.x * blockDim.x + threadIdx.x;
    if (t >= N_TOK) return;
    int e = g_idx[t];
    int p = atomicAdd(&g_cursor[e], 1);
    g_perm[g_offset[e] + p] = t;
}

// ---------------------------------------------------------------- fp16 grouped GEMM
// (verbatim R5 — verified 598 us configuration)
// 8 warps = 4(M) x 2(N); warp tile 32 x 64; CTA tile 128 x 128, BK=32 halves.
// MODE 0: g_hh = fp16(gelu(g_xh[perm] @ W1[e] + b1[e]))  K=1024, NDIM=4096
// MODE 1: out[token] = prob * (g_hh @ W2[e] + b2[e])     K=4096, NDIM=1024
template <int MODE>
__global__ void __launch_bounds__(256)
moe_gemm_k(const __half* __restrict__ Ain, const __half* __restrict__ W,
           const float* __restrict__ bias, float* __restrict__ OutG,
           int K, int NDIM) {
    __shared__ __half As[2][BM * ASTRIDE];
    __shared__ __half Bs[2][BK * BSTRIDE];

    int mt = blockIdx.x;
    if (mt >= g_numTiles) return;
    int e      = g_tileExpert[mt];
    int gstart = g_tileStart[mt];
    int mcount = g_tileCount[mt];
    int n0     = blockIdx.y * 128;

    const __half* We = W + (size_t)e * K * NDIM;

    int tid = threadIdx.x, lane = tid & 31, warp = tid >> 5;
    int wm = warp & 3;        // 4 warps along M (32 rows)
    int wn = warp >> 2;       // 2 warps along N (64 cols)
    int gid = lane >> 2, tig = lane & 3;

    // ---- A loads: row = tid>>1, 32B of the 64B row per thread (2 x cp16)
    int arow = tid >> 1;
    int ach  = (tid & 1) * 16;
    bool va  = arow < mcount;
    const __half* pA;
    if (MODE == 0) {
        int t0 = va ? g_perm[gstart + arow] : g_perm[gstart];
        pA = Ain + (size_t)t0 * K + ach;
    } else {
        int r0 = va ? (gstart + arow) : gstart;
        pA = Ain + (size_t)r0 * K + ach;
    }
    // ---- B loads: row = tid>>3 (0..31), 32B of the 256B row per thread
    int brow = tid >> 3;
    int bch  = (tid & 7) * 16;
    const __half* pB = We + (size_t)brow * NDIM + n0 + bch;

    uint32_t sAd[2], sBd[2];
#pragma unroll
    for (int st = 0; st < 2; st++) {
        sAd[st] = (uint32_t)__cvta_generic_to_shared(&As[st][arow * ASTRIDE + ach]);
        sBd[st] = (uint32_t)__cvta_generic_to_shared(&Bs[st][brow * BSTRIDE + bch]);
    }

    // ---- ldmatrix lane addresses (byte offsets within one stage buffer)
    uint32_t aoff = ((wm * 32 + (lane & 15)) * ASTRIDE + (lane >> 4) * 8) * 2;
    uint32_t boff = (((lane & 7) + ((lane >> 3) & 1) * 8) * BSTRIDE +
                     wn * 64 + (lane >> 4) * 8) * 2;
    uint32_t aBase[2], bBase[2];
#pragma unroll
    for (int st = 0; st < 2; st++) {
        aBase[st] = (uint32_t)__cvta_generic_to_shared(&As[st][0]) + aoff;
        bBase[st] = (uint32_t)__cvta_generic_to_shared(&Bs[st][0]) + boff;
    }

    float acc[2][8][4];
#pragma unroll
    for (int mi = 0; mi < 2; mi++)
#pragma unroll
        for (int ni = 0; ni < 8; ni++)
#pragma unroll
            for (int j = 0; j < 4; j++) acc[mi][ni][j] = 0.f;

    int nsteps = K / BK;

    // prefetch stage 0
    cp16(sAd[0],      pA,     va);
    cp16(sAd[0] + 16, pA + 8, va);
    cp16(sBd[0],      pB,     true);
    cp16(sBd[0] + 16, pB + 8, true);
    asm volatile("cp.async.commit_group;\n" ::: "memory");

    for (int s = 0; s < nsteps; s++) {
        if (s + 1 < nsteps) {
            int st = (s + 1) & 1;
            size_t ka = (size_t)(s + 1) * BK;
            size_t kb = (size_t)(s + 1) * BK * NDIM;
            cp16(sAd[st],      pA + ka,     va);
            cp16(sAd[st] + 16, pA + ka + 8, va);
            cp16(sBd[st],      pB + kb,     true);
            cp16(sBd[st] + 16, pB + kb + 8, true);
            asm volatile("cp.async.commit_group;\n" ::: "memory");
            asm volatile("cp.async.wait_group 1;\n" ::: "memory");
        } else {
            asm volatile("cp.async.wait_group 0;\n" ::: "memory");
        }
        __syncthreads();
        int st = s & 1;
#pragma unroll
        for (int kk = 0; kk < 2; kk++) {
            uint32_t a[2][4];
#pragma unroll
            for (int mi = 0; mi < 2; mi++)
                ldsm4(a[mi][0], a[mi][1], a[mi][2], a[mi][3],
                      aBase[st] + (mi * 16 * ASTRIDE + kk * 16) * 2);
            uint32_t b[8][2];
#pragma unroll
            for (int t = 0; t < 4; t++) {
                uint32_t r0, r1, r2, r3;
                ldsm4t(r0, r1, r2, r3,
                       bBase[st] + (kk * 16 * BSTRIDE + t * 16) * 2);
                b[2 * t][0] = r0; b[2 * t][1] = r1;
                b[2 * t + 1][0] = r2; b[2 * t + 1][1] = r3;
            }
#pragma unroll
            for (int mi = 0; mi < 2; mi++)
#pragma unroll
                for (int ni = 0; ni < 8; ni++) {
                    asm volatile(
                        "mma.sync.aligned.m16n8k16.row.col.f32.f16.f16.f32 "
                        "{%0,%1,%2,%3}, {%4,%5,%6,%7}, {%8,%9}, {%0,%1,%2,%3};\n"
                        : "+f"(acc[mi][ni][0]), "+f"(acc[mi][ni][1]),
                          "+f"(acc[mi][ni][2]), "+f"(acc[mi][ni][3])
                        : "r"(a[mi][0]), "r"(a[mi][1]), "r"(a[mi][2]), "r"(a[mi][3]),
                          "r"(b[ni][0]), "r"(b[ni][1]));
                }
        }
        __syncthreads();
    }

    // ---- epilogue (C frag: rows gid, gid+8; cols tig*2, tig*2+1)
#pragma unroll
    for (int mi = 0; mi < 2; mi++) {
        int rlo = wm * 32 + mi * 16 + gid;
        int rhi = rlo + 8;
        bool vlo = rlo < mcount, vhi = rhi < mcount;
        size_t dlo = 0, dhi = 0;
        float glo = 1.f, ghi = 1.f;
        if (MODE == 0) {
            dlo = (size_t)(gstart + rlo) * NDIM;
            dhi = (size_t)(gstart + rhi) * NDIM;
        } else {
            int tlo = vlo ? g_perm[gstart + rlo] : 0;
            int thi = vhi ? g_perm[gstart + rhi] : 0;
            glo = g_prob[tlo];
            ghi = g_prob[thi];
            dlo = (size_t)tlo * NDIM;
            dhi = (size_t)thi * NDIM;
        }
#pragma unroll
        for (int ni = 0; ni < 8; ni++) {
            int col = n0 + wn * 64 + ni * 8 + tig * 2;
            float bz0 = bias[(size_t)e * NDIM + col];
            float bz1 = bias[(size_t)e * NDIM + col + 1];
            float v00 = acc[mi][ni][0] + bz0, v01 = acc[mi][ni][1] + bz1;
            float v10 = acc[mi][ni][2] + bz0, v11 = acc[mi][ni][3] + bz1;
            if (MODE == 0) {
                if (vlo) *(__half2*)&g_hh[dlo + col] =
                    __floats2half2_rn(gelu_f(v00), gelu_f(v01));
                if (vhi) *(__half2*)&g_hh[dhi + col] =
                    __floats2half2_rn(gelu_f(v10), gelu_f(v11));
            } else {
                if (vlo) *(float2*)&OutG[dlo + col] = make_float2(glo * v00, glo * v01);
                if (vhi) *(float2*)&OutG[dhi + col] = make_float2(ghi * v10, ghi * v11);
            }
        }
    }
}

// ---------------------------------------------------------------- launch
extern "C" void kernel_launch(void* const* d_in, const int* in_sizes, int n_in,
                              void* d_out, int out_size) {
    const float* x  = (const float*)d_in[0];
    const float* Wr = (const float*)d_in[1];
    const float* br = (const float*)d_in[2];
    const float* W1 = (const float*)d_in[3];
    const float* b1 = (const float*)d_in[4];
    const float* W2 = (const float*)d_in[5];
    const float* b2 = (const float*)d_in[6];
    float* out = (float*)d_out;

    __half *xh, *w1h, *w2h, *hh;
    cudaGetSymbolAddress((void**)&xh,  g_xh);
    cudaGetSymbolAddress((void**)&w1h, g_w1h);
    cudaGetSymbolAddress((void**)&w2h, g_w2h);
    cudaGetSymbolAddress((void**)&hh,  g_hh);

    router_k<<<N_TOK * 32 / 256, 256>>>(x, Wr, br);
    cvt_h_k<<<2048, 256>>>(x, xh, N_TOK * CDIM / 4);
    cvt_w_k<<<16384, 256>>>(W1, w1h, W2, w2h);
    setup_k<<<1, 256>>>(out, out_size);
    scatter_k<<<N_TOK / 256, 256>>>();
    // grid.x = m-tile slot (<=71 used), grid.y = n-block; x-fastest keeps one
    // weight column-block resident in L2 across all concurrent m-tiles.
    moe_gemm_k<0><<<dim3(72, HDIM / 128), 256>>>(xh, w1h, b1, nullptr, CDIM, HDIM);
    moe_gemm_k<1><<<dim3(72, CDIM / 128), 256>>>(hh, w2h, b2, out,     HDIM, CDIM);
}

// round 12
// speedup vs baseline: 1.5390x; 1.0128x over previous
#include <cuda_runtime.h>
#include <cuda_fp16.h>
#include <cstdint>

#define N_TOK 8192
#define CDIM  1024
#define HDIM  4096
#define NEXP  8
#define BM    128
#define BK    32
#define MAXTILES 80
#define ASTRIDE 40    // halves per A smem row (80 B): conflict-free ldsm
#define BSTRIDE 136   // halves per B smem row (272 B): conflict-free ldsm
#define W_N4 (NEXP * CDIM * HDIM / 4)   // float4 count per weight tensor
#define X_N4 (N_TOK * CDIM / 4)

// prep_k block partition: [0,1024) router | [1024,1280) x-cvt |
// [1280,3328) W1-cvt | [3328,5376) W2-cvt
#define RTR_BLKS  1024
#define XC_BLKS   256
#define WC_BLKS   2048
#define PREP_BLKS (RTR_BLKS + XC_BLKS + 2 * WC_BLKS)

// ---- scratch (static __device__ — allocation-free per harness rules) ----
__device__ __half g_hh [(size_t)N_TOK * HDIM];           // fc1 act (fp16), sorted order
__device__ __half g_xh [(size_t)N_TOK * CDIM];           // x in fp16
__device__ __half g_w1h[(size_t)NEXP * CDIM * HDIM];     // W1 fp16
__device__ __half g_w2h[(size_t)NEXP * HDIM * CDIM];     // W2 fp16
__device__ int    g_idx[N_TOK];
__device__ float  g_prob[N_TOK];
__device__ int    g_perm[N_TOK];
__device__ int    g_cursor[NEXP];
__device__ int    g_offset[NEXP + 1];
__device__ int    g_tileExpert[MAXTILES];
__device__ int    g_tileStart[MAXTILES];
__device__ int    g_tileCount[MAXTILES];
__device__ int    g_numTiles;

// ---------------------------------------------------------------- helpers
__device__ __forceinline__ float gelu_f(float v) {
    return 0.5f * v * (1.0f + erff(v * 0.70710678118654752f));
}
__device__ __forceinline__ void cp16(uint32_t dst, const void* src, bool pred) {
    int sz = pred ? 16 : 0;  // src-size 0 => zero-fill 16B
    asm volatile("cp.async.ca.shared.global [%0], [%1], 16, %2;\n"
                 :: "r"(dst), "l"(src), "r"(sz));
}
__device__ __forceinline__ void ldsm4(uint32_t& r0, uint32_t& r1, uint32_t& r2,
                                      uint32_t& r3, uint32_t addr) {
    asm volatile("ldmatrix.sync.aligned.m8n8.x4.shared.b16 {%0,%1,%2,%3}, [%4];"
                 : "=r"(r0), "=r"(r1), "=r"(r2), "=r"(r3) : "r"(addr));
}
__device__ __forceinline__ void ldsm4t(uint32_t& r0, uint32_t& r1, uint32_t& r2,
                                       uint32_t& r3, uint32_t addr) {
    asm volatile("ldmatrix.sync.aligned.m8n8.x4.trans.shared.b16 {%0,%1,%2,%3}, [%4];"
                 : "=r"(r0), "=r"(r1), "=r"(r2), "=r"(r3) : "r"(addr));
}
// block-partitioned grid-stride fp32 -> fp16 convert
__device__ __forceinline__ void conv_range(const float* __restrict__ src,
                                           __half* __restrict__ dst, int n4,
                                           int blk, int nblk) {
    const float4* s = (const float4*)src;
    __half2* d = (__half2*)dst;
    int stride = nblk * blockDim.x;
    for (int i = blk * blockDim.x + threadIdx.x; i < n4; i += stride) {
        float4 v = s[i];
        d[2 * i]     = __floats2half2_rn(v.x, v.y);
        d[2 * i + 1] = __floats2half2_rn(v.z, v.w);
    }
}

// ---------------------------------------------------------------- prep
// router blocks carry the VERBATIM R5/R10 router body (one warp per token);
// trailing blocks stream the fp32->fp16 conversions (independent work).
__global__ void prep_k(const float* __restrict__ x, const float* __restrict__ Wr,
                       const float* __restrict__ br, __half* __restrict__ xh,
                       const float* __restrict__ W1, __half* __restrict__ w1h,
                       const float* __restrict__ W2, __half* __restrict__ w2h) {
    int b = blockIdx.x;
    if (b >= RTR_BLKS) {
        int cb = b - RTR_BLKS;
        if (cb < XC_BLKS)
            conv_range(x, xh, X_N4, cb, XC_BLKS);
        else if (cb < XC_BLKS + WC_BLKS)
            conv_range(W1, w1h, W_N4, cb - XC_BLKS, WC_BLKS);
        else
            conv_range(W2, w2h, W_N4, cb - XC_BLKS - WC_BLKS, WC_BLKS);
        return;
    }
    int gt = b * blockDim.x + threadIdx.x;
    int tok = gt >> 5, lane = gt & 31;
    const float* xr = x + (size_t)tok * CDIM;
    float s[NEXP];
#pragma unroll
    for (int e = 0; e < NEXP; e++) s[e] = 0.f;
    for (int k = lane; k < CDIM; k += 32) {
        float xv = xr[k];
        const float4* w = (const float4*)(Wr + (size_t)k * NEXP);
        float4 w0 = w[0], w1 = w[1];
        s[0] += xv * w0.x; s[1] += xv * w0.y; s[2] += xv * w0.z; s[3] += xv * w0.w;
        s[4] += xv * w1.x; s[5] += xv * w1.y; s[6] += xv * w1.z; s[7] += xv * w1.w;
    }
#pragma unroll
    for (int e = 0; e < NEXP; e++)
#pragma unroll
        for (int o = 16; o > 0; o >>= 1) s[e] += __shfl_xor_sync(0xffffffffu, s[e], o);
    if (lane == 0) {
        float l[NEXP];
        l[0] = s[0] + br[0];
        float m = l[0]; int mi = 0;
#pragma unroll
        for (int e = 1; e < NEXP; e++) {
            l[e] = s[e] + br[e];
            if (l[e] > m) { m = l[e]; mi = e; }
        }
        float sum = 0.f;
#pragma unroll
        for (int e = 0; e < NEXP; e++) sum += expf(l[e] - m);
        g_prob[tok] = 1.0f / sum;
        g_idx[tok] = mi;
    }
}

// setup: count assignments from g_idx (smem atomics), build tile table,
// zero scatter cursors, write aux loss. One block, 256 threads.
__global__ void setup_k(float* out, int out_size) {
    __shared__ int cnt[NEXP];
    int tid = threadIdx.x;
    if (tid < NEXP) cnt[tid] = 0;
    __syncthreads();
    for (int i = tid; i < N_TOK; i += blockDim.x)
        atomicAdd(&cnt[g_idx[i]], 1);
    __syncthreads();
    if (tid == 0) {
        int off = 0, nt = 0;
        for (int e = 0; e < NEXP; e++) {
            g_offset[e] = off;
            g_cursor[e] = 0;
            int c = cnt[e];
            int t = (c + BM - 1) / BM;
            for (int i = 0; i < t; i++) {
                g_tileExpert[nt] = e;
                g_tileStart[nt] = off + i * BM;
                int rem = c - i * BM;
                g_tileCount[nt] = rem < BM ? rem : BM;
                nt++;
            }
            off += c;
        }
        g_offset[NEXP] = off;
        g_numTiles = nt;
        float aux = 0.f, tot = (float)off;
        if (tot < 1.f) tot = 1.f;
        for (int e = 0; e < NEXP; e++) {
            float d = (float)cnt[e] / tot - 1.0f / NEXP;
            aux += d * d;
        }
        aux *= 1.0f / NEXP;
        if (out_size > N_TOK * CDIM) out[(size_t)N_TOK * CDIM] = aux;
    }
}

__global__ void scatter_k() {
    int t = blockIdx.x * blockDim.x + threadIdx.x;
    if (t >= N_TOK) return;
    int e = g_idx[t];
    int p = atomicAdd(&g_cursor[e], 1);
    g_perm[g_offset[e] + p] = t;
}

// ---------------------------------------------------------------- fp16 grouped GEMM
// (verbatim R5/R10 — verified 596 us configuration)
// 8 warps = 4(M) x 2(N); warp tile 32 x 64; CTA tile 128 x 128, BK=32 halves.
// MODE 0: g_hh = fp16(gelu(g_xh[perm] @ W1[e] + b1[e]))  K=1024, NDIM=4096
// MODE 1: out[token] = prob * (g_hh @ W2[e] + b2[e])     K=4096, NDIM=1024
template <int MODE>
__global__ void __launch_bounds__(256)
moe_gemm_k(const __half* __restrict__ Ain, const __half* __restrict__ W,
           const float* __restrict__ bias, float* __restrict__ OutG,
           int K, int NDIM) {
    __shared__ __half As[2][BM * ASTRIDE];
    __shared__ __half Bs[2][BK * BSTRIDE];

    int mt = blockIdx.x;
    if (mt >= g_numTiles) return;
    int e      = g_tileExpert[mt];
    int gstart = g_tileStart[mt];
    int mcount = g_tileCount[mt];
    int n0     = blockIdx.y * 128;

    const __half* We = W + (size_t)e * K * NDIM;

    int tid = threadIdx.x, lane = tid & 31, warp = tid >> 5;
    int wm = warp & 3;        // 4 warps along M (32 rows)
    int wn = warp >> 2;       // 2 warps along N (64 cols)
    int gid = lane >> 2, tig = lane & 3;

    // ---- A loads: row = tid>>1, 32B of the 64B row per thread (2 x cp16)
    int arow = tid >> 1;
    int ach  = (tid & 1) * 16;
    bool va  = arow < mcount;
    const __half* pA;
    if (MODE == 0) {
        int t0 = va ? g_perm[gstart + arow] : g_perm[gstart];
        pA = Ain + (size_t)t0 * K + ach;
    } else {
        int r0 = va ? (gstart + arow) : gstart;
        pA = Ain + (size_t)r0 * K + ach;
    }
    // ---- B loads: row = tid>>3 (0..31), 32B of the 256B row per thread
    int brow = tid >> 3;
    int bch  = (tid & 7) * 16;
    const __half* pB = We + (size_t)brow * NDIM + n0 + bch;

    uint32_t sAd[2], sBd[2];
#pragma unroll
    for (int st = 0; st < 2; st++) {
        sAd[st] = (uint32_t)__cvta_generic_to_shared(&As[st][arow * ASTRIDE + ach]);
        sBd[st] = (uint32_t)__cvta_generic_to_shared(&Bs[st][brow * BSTRIDE + bch]);
    }

    // ---- ldmatrix lane addresses (byte offsets within one stage buffer)
    uint32_t aoff = ((wm * 32 + (lane & 15)) * ASTRIDE + (lane >> 4) * 8) * 2;
    uint32_t boff = (((lane & 7) + ((lane >> 3) & 1) * 8) * BSTRIDE +
                     wn * 64 + (lane >> 4) * 8) * 2;
    uint32_t aBase[2], bBase[2];
#pragma unroll
    for (int st = 0; st < 2; st++) {
        aBase[st] = (uint32_t)__cvta_generic_to_shared(&As[st][0]) + aoff;
        bBase[st] = (uint32_t)__cvta_generic_to_shared(&Bs[st][0]) + boff;
    }

    float acc[2][8][4];
#pragma unroll
    for (int mi = 0; mi < 2; mi++)
#pragma unroll
        for (int ni = 0; ni < 8; ni++)
#pragma unroll
            for (int j = 0; j < 4; j++) acc[mi][ni][j] = 0.f;

    int nsteps = K / BK;

    // prefetch stage 0
    cp16(sAd[0],      pA,     va);
    cp16(sAd[0] + 16, pA + 8, va);
    cp16(sBd[0],      pB,     true);
    cp16(sBd[0] + 16, pB + 8, true);
    asm volatile("cp.async.commit_group;\n" ::: "memory");

    for (int s = 0; s < nsteps; s++) {
        if (s + 1 < nsteps) {
            int st = (s + 1) & 1;
            size_t ka = (size_t)(s + 1) * BK;
            size_t kb = (size_t)(s + 1) * BK * NDIM;
            cp16(sAd[st],      pA + ka,     va);
            cp16(sAd[st] + 16, pA + ka + 8, va);
            cp16(sBd[st],      pB + kb,     true);
            cp16(sBd[st] + 16, pB + kb + 8, true);
            asm volatile("cp.async.commit_group;\n" ::: "memory");
            asm volatile("cp.async.wait_group 1;\n" ::: "memory");
        } else {
            asm volatile("cp.async.wait_group 0;\n" ::: "memory");
        }
        __syncthreads();
        int st = s & 1;
#pragma unroll
        for (int kk = 0; kk < 2; kk++) {
            uint32_t a[2][4];
#pragma unroll
            for (int mi = 0; mi < 2; mi++)
                ldsm4(a[mi][0], a[mi][1], a[mi][2], a[mi][3],
                      aBase[st] + (mi * 16 * ASTRIDE + kk * 16) * 2);
            uint32_t b[8][2];
#pragma unroll
            for (int t = 0; t < 4; t++) {
                uint32_t r0, r1, r2, r3;
                ldsm4t(r0, r1, r2, r3,
                       bBase[st] + (kk * 16 * BSTRIDE + t * 16) * 2);
                b[2 * t][0] = r0; b[2 * t][1] = r1;
                b[2 * t + 1][0] = r2; b[2 * t + 1][1] = r3;
            }
#pragma unroll
            for (int mi = 0; mi < 2; mi++)
#pragma unroll
                for (int ni = 0; ni < 8; ni++) {
                    asm volatile(
                        "mma.sync.aligned.m16n8k16.row.col.f32.f16.f16.f32 "
                        "{%0,%1,%2,%3}, {%4,%5,%6,%7}, {%8,%9}, {%0,%1,%2,%3};\n"
                        : "+f"(acc[mi][ni][0]), "+f"(acc[mi][ni][1]),
                          "+f"(acc[mi][ni][2]), "+f"(acc[mi][ni][3])
                        : "r"(a[mi][0]), "r"(a[mi][1]), "r"(a[mi][2]), "r"(a[mi][3]),
                          "r"(b[ni][0]), "r"(b[ni][1]));
                }
        }
        __syncthreads();
    }

    // ---- epilogue (C frag: rows gid, gid+8; cols tig*2, tig*2+1)
#pragma unroll
    for (int mi = 0; mi < 2; mi++) {
        int rlo = wm * 32 + mi * 16 + gid;
        int rhi = rlo + 8;
        bool vlo = rlo < mcount, vhi = rhi < mcount;
        size_t dlo = 0, dhi = 0;
        float glo = 1.f, ghi = 1.f;
        if (MODE == 0) {
            dlo = (size_t)(gstart + rlo) * NDIM;
            dhi = (size_t)(gstart + rhi) * NDIM;
        } else {
            int tlo = vlo ? g_perm[gstart + rlo] : 0;
            int thi = vhi ? g_perm[gstart + rhi] : 0;
            glo = g_prob[tlo];
            ghi = g_prob[thi];
            dlo = (size_t)tlo * NDIM;
            dhi = (size_t)thi * NDIM;
        }
#pragma unroll
        for (int ni = 0; ni < 8; ni++) {
            int col = n0 + wn * 64 + ni * 8 + tig * 2;
            float bz0 = bias[(size_t)e * NDIM + col];
            float bz1 = bias[(size_t)e * NDIM + col + 1];
            float v00 = acc[mi][ni][0] + bz0, v01 = acc[mi][ni][1] + bz1;
            float v10 = acc[mi][ni][2] + bz0, v11 = acc[mi][ni][3] + bz1;
            if (MODE == 0) {
                if (vlo) *(__half2*)&g_hh[dlo + col] =
                    __floats2half2_rn(gelu_f(v00), gelu_f(v01));
                if (vhi) *(__half2*)&g_hh[dhi + col] =
                    __floats2half2_rn(gelu_f(v10), gelu_f(v11));
            } else {
                if (vlo) *(float2*)&OutG[dlo + col] = make_float2(glo * v00, glo * v01);
                if (vhi) *(float2*)&OutG[dhi + col] = make_float2(ghi * v10, ghi * v11);
            }
        }
    }
}

// ---------------------------------------------------------------- launch
extern "C" void kernel_launch(void* const* d_in, const int* in_sizes, int n_in,
                              void* d_out, int out_size) {
    const float* x  = (const float*)d_in[0];
    const float* Wr = (const float*)d_in[1];
    const float* br = (const float*)d_in[2];
    const float* W1 = (const float*)d_in[3];
    const float* b1 = (const float*)d_in[4];
    const float* W2 = (const float*)d_in[5];
    const float* b2 = (const float*)d_in[6];
    float* out = (float*)d_out;

    __half *xh, *w1h, *w2h, *hh;
    cudaGetSymbolAddress((void**)&xh,  g_xh);
    cudaGetSymbolAddress((void**)&w1h, g_w1h);
    cudaGetSymbolAddress((void**)&w2h, g_w2h);
    cudaGetSymbolAddress((void**)&hh,  g_hh);

    prep_k<<<PREP_BLKS, 256>>>(x, Wr, br, xh, W1, w1h, W2, w2h);
    setup_k<<<1, 256>>>(out, out_size);
    scatter_k<<<N_TOK / 256, 256>>>();
    // grid.x = m-tile slot (<=71 used), grid.y = n-block; x-fastest keeps one
    // weight column-block resident in L2 across all concurrent m-tiles.
    moe_gemm_k<0><<<dim3(72, HDIM / 128), 256>>>(xh, w1h, b1, nullptr, CDIM, HDIM);
    moe_gemm_k<1><<<dim3(72, CDIM / 128), 256>>>(hh, w2h, b2, out,     HDIM, CDIM);
}